// round 1
// baseline (speedup 1.0000x reference)
#include <cuda_runtime.h>
#include <cuda_bf16.h>
#include <math.h>

#define NB   64      // batch
#define PP   256     // patches
#define DV   1024
#define DT   768
#define SS   512     // seq len
#define NSEG 32
#define PPT  8

// ---------------- scratch (device globals; no allocation allowed) -----------
static __device__ float g_segn[NB * NSEG * DV];     // 8 MB: per-segment sum of layernormed patches
static __device__ float g_segmean[NB * NSEG * DT];  // 6 MB: segment means after projection
static __device__ float g_nrm[NB * DT];
static __device__ float g_sim[NB * NB];
static __device__ int   g_rank[NB * SS];

// ---------------- 1) LayerNorm + segment sum --------------------------------
// grid = NB*NSEG blocks, 256 threads. Each block: 8 patches x 1024 dims.
__global__ void k_ln_segsum(const float* __restrict__ vis,
                            const float* __restrict__ gamma,
                            const float* __restrict__ beta) {
    int bs  = blockIdx.x;                 // b*NSEG + seg
    int tid = threadIdx.x;
    int lane = tid & 31, warp = tid >> 5;
    __shared__ float rs[8], rq[8], bc[2];

    const float* base = vis + (size_t)bs * PPT * DV;
    int d0 = tid * 4;
    float4 g  = *(const float4*)(gamma + d0);
    float4 be = *(const float4*)(beta  + d0);
    float a0 = 0.f, a1 = 0.f, a2 = 0.f, a3 = 0.f;

    for (int p = 0; p < PPT; ++p) {
        float4 x = *(const float4*)(base + p * DV + d0);
        float s = x.x + x.y + x.z + x.w;
        float q = x.x * x.x + x.y * x.y + x.z * x.z + x.w * x.w;
        #pragma unroll
        for (int o = 16; o > 0; o >>= 1) {
            s += __shfl_xor_sync(0xffffffffu, s, o);
            q += __shfl_xor_sync(0xffffffffu, q, o);
        }
        if (lane == 0) { rs[warp] = s; rq[warp] = q; }
        __syncthreads();
        if (warp == 0) {
            float s2 = lane < 8 ? rs[lane] : 0.f;
            float q2 = lane < 8 ? rq[lane] : 0.f;
            #pragma unroll
            for (int o = 4; o > 0; o >>= 1) {
                s2 += __shfl_xor_sync(0xffffffffu, s2, o);
                q2 += __shfl_xor_sync(0xffffffffu, q2, o);
            }
            if (lane == 0) {
                float mean = s2 * (1.f / DV);
                float var  = q2 * (1.f / DV) - mean * mean;
                bc[0] = mean;
                bc[1] = rsqrtf(var + 1e-5f);
            }
        }
        __syncthreads();
        float mean = bc[0], rstd = bc[1];
        a0 += (x.x - mean) * rstd * g.x + be.x;
        a1 += (x.y - mean) * rstd * g.y + be.y;
        a2 += (x.z - mean) * rstd * g.z + be.z;
        a3 += (x.w - mean) * rstd * g.w + be.w;
    }
    *(float4*)(g_segn + (size_t)bs * DV + d0) = make_float4(a0, a1, a2, a3);
}

// ---------------- 2) GEMM: segmean = (segn @ W)/8 + b_proj ------------------
// A [2048,1024] x W [1024,768]. BM=128 BN=64 BK=16, 256 thr, 8x4 per thread.
#define BM 128
#define BN 64
#define BK 16
#define AST 132
#define BST 68
__global__ __launch_bounds__(256) void k_gemm(const float* __restrict__ W,
                                              const float* __restrict__ bproj) {
    __shared__ float As[BK][AST];   // transposed A tile: As[k][m]
    __shared__ float Bs[BK][BST];   // Bs[k][n]
    int tid = threadIdx.x;
    int m0 = blockIdx.y * BM;
    int n0 = blockIdx.x * BN;
    int tx = tid & 15, ty = tid >> 4;

    float acc[8][4];
    #pragma unroll
    for (int i = 0; i < 8; ++i)
        #pragma unroll
        for (int j = 0; j < 4; ++j) acc[i][j] = 0.f;

    const float* A = g_segn;

    for (int k0 = 0; k0 < DV; k0 += BK) {
        // load A tile (128x16 floats = 512 float4; 2 per thread), transpose into As
        #pragma unroll
        for (int i = 0; i < 2; ++i) {
            int f    = tid + i * 256;
            int row  = f >> 2;
            int colf = f & 3;
            float4 v = *(const float4*)(A + (size_t)(m0 + row) * DV + k0 + colf * 4);
            As[colf * 4 + 0][row] = v.x;
            As[colf * 4 + 1][row] = v.y;
            As[colf * 4 + 2][row] = v.z;
            As[colf * 4 + 3][row] = v.w;
        }
        // load B tile (16x64 floats = 256 float4; 1 per thread)
        {
            int row  = tid >> 4;
            int colf = tid & 15;
            float4 v = *(const float4*)(W + (size_t)(k0 + row) * DT + n0 + colf * 4);
            *(float4*)&Bs[row][colf * 4] = v;
        }
        __syncthreads();
        #pragma unroll
        for (int kk = 0; kk < BK; ++kk) {
            float4 a0 = *(const float4*)&As[kk][ty * 8];
            float4 a1 = *(const float4*)&As[kk][ty * 8 + 4];
            float4 b  = *(const float4*)&Bs[kk][tx * 4];
            float av[8] = {a0.x, a0.y, a0.z, a0.w, a1.x, a1.y, a1.z, a1.w};
            float bv[4] = {b.x, b.y, b.z, b.w};
            #pragma unroll
            for (int i = 0; i < 8; ++i)
                #pragma unroll
                for (int j = 0; j < 4; ++j) acc[i][j] += av[i] * bv[j];
        }
        __syncthreads();
    }

    float4 bp = *(const float4*)(bproj + n0 + tx * 4);
    #pragma unroll
    for (int i = 0; i < 8; ++i) {
        int m = m0 + ty * 8 + i;
        float4 o;
        o.x = acc[i][0] * 0.125f + bp.x;
        o.y = acc[i][1] * 0.125f + bp.y;
        o.z = acc[i][2] * 0.125f + bp.z;
        o.w = acc[i][3] * 0.125f + bp.w;
        *(float4*)(g_segmean + (size_t)m * DT + n0 + tx * 4) = o;
    }
}

// ---------------- 3) pooled = mean of seg_means, then L2-normalize ----------
__global__ void k_pool() {
    int b = blockIdx.x;
    int tid = threadIdx.x;     // 256 threads, 3 dims each
    int lane = tid & 31, warp = tid >> 5;
    __shared__ float red[8], bn;
    float p[3];
    #pragma unroll
    for (int c = 0; c < 3; ++c) {
        int d = tid + c * 256;
        float s = 0.f;
        for (int sg = 0; sg < NSEG; ++sg)
            s += g_segmean[((size_t)b * NSEG + sg) * DT + d];
        p[c] = s * (1.f / NSEG);
    }
    float q = p[0] * p[0] + p[1] * p[1] + p[2] * p[2];
    #pragma unroll
    for (int o = 16; o > 0; o >>= 1) q += __shfl_xor_sync(0xffffffffu, q, o);
    if (lane == 0) red[warp] = q;
    __syncthreads();
    if (warp == 0) {
        float q2 = lane < 8 ? red[lane] : 0.f;
        #pragma unroll
        for (int o = 4; o > 0; o >>= 1) q2 += __shfl_xor_sync(0xffffffffu, q2, o);
        if (lane == 0) bn = 1.f / sqrtf(q2);
    }
    __syncthreads();
    float inv = bn;
    #pragma unroll
    for (int c = 0; c < 3; ++c)
        g_nrm[(size_t)b * DT + tid + c * 256] = p[c] * inv;
}

// ---------------- 4) sim = (nrm @ nrm^T) / TEMP -----------------------------
__global__ void k_sim() {
    int i = blockIdx.x;
    int tid = threadIdx.x;     // 256 = 8 warps
    int warp = tid >> 5, lane = tid & 31;
    __shared__ float ni[DT];
    for (int d = tid; d < DT; d += 256) ni[d] = g_nrm[(size_t)i * DT + d];
    __syncthreads();
    for (int jb = 0; jb < 8; ++jb) {
        int j = jb * 8 + warp;
        const float* nj = g_nrm + (size_t)j * DT;
        float s = 0.f;
        for (int d = lane; d < DT; d += 32) s += ni[d] * nj[d];
        #pragma unroll
        for (int o = 16; o > 0; o >>= 1) s += __shfl_xor_sync(0xffffffffu, s, o);
        if (lane == 0) g_sim[i * NB + j] = s / 0.07f;
    }
}

// ---------------- 5) symmetric InfoNCE loss ---------------------------------
__global__ void k_loss(float* __restrict__ out) {
    int i = threadIdx.x;  // 64 threads
    __shared__ float red[64];
    float diag = g_sim[i * NB + i];
    // row
    float m = -1e30f;
    for (int j = 0; j < NB; ++j) m = fmaxf(m, g_sim[i * NB + j]);
    float se = 0.f;
    for (int j = 0; j < NB; ++j) se += expf(g_sim[i * NB + j] - m);
    float rl = (m + logf(se)) - diag;
    // col
    float mc = -1e30f;
    for (int j = 0; j < NB; ++j) mc = fmaxf(mc, g_sim[j * NB + i]);
    float sc = 0.f;
    for (int j = 0; j < NB; ++j) sc += expf(g_sim[j * NB + i] - mc);
    float cl = (mc + logf(sc)) - diag;

    red[i] = rl + cl;
    __syncthreads();
    #pragma unroll
    for (int o = 32; o > 0; o >>= 1) {
        if (i < o) red[i] += red[i + o];
        __syncthreads();
    }
    if (i == 0) out[0] = red[0] * (0.5f / NB);
}

// ---------------- 6) per-row placeholder rank (inclusive scan) --------------
__global__ void k_rank(const int* __restrict__ ids, const int* __restrict__ phid) {
    int b = blockIdx.x, s = threadIdx.x;  // 512 threads
    __shared__ int sc[SS];
    int ph = phid[0];
    int m = (ids[b * SS + s] == ph) ? 1 : 0;
    sc[s] = m;
    __syncthreads();
    for (int o = 1; o < SS; o <<= 1) {
        int v = (s >= o) ? sc[s - o] : 0;
        __syncthreads();
        sc[s] += v;
        __syncthreads();
    }
    int rank = sc[s] - 1;
    g_rank[b * SS + s] = (m && rank < NSEG) ? rank : -1;
}

// ---------------- 7) text_emb assembly (gather wte or seg_means) ------------
__global__ void k_text(const float* __restrict__ wte, const int* __restrict__ ids,
                       float* __restrict__ out) {
    int bs  = blockIdx.x;         // b*SS + s
    int tid = threadIdx.x;        // 192 threads, one float4 each (768 floats)
    int r = g_rank[bs];
    const float4* src;
    if (r >= 0) {
        int b = bs / SS;
        src = (const float4*)(g_segmean + ((size_t)(b * NSEG + r)) * DT);
    } else {
        src = (const float4*)(wte + (size_t)ids[bs] * DT);
    }
    ((float4*)out)[(size_t)bs * (DT / 4) + tid] = src[tid];
}

// ---------------- launch ----------------------------------------------------
extern "C" void kernel_launch(void* const* d_in, const int* in_sizes, int n_in,
                              void* d_out, int out_size) {
    const float* vis   = (const float*)d_in[0];
    const float* gamma = (const float*)d_in[1];
    const float* beta  = (const float*)d_in[2];
    const float* W     = (const float*)d_in[3];
    const float* bproj = (const float*)d_in[4];
    const float* wte   = (const float*)d_in[5];
    const int*   ids   = (const int*)d_in[6];
    const int*   phid  = (const int*)d_in[7];
    float* out = (float*)d_out;

    k_ln_segsum<<<NB * NSEG, 256>>>(vis, gamma, beta);
    k_gemm<<<dim3(DT / BN, (NB * NSEG) / BM), 256>>>(W, bproj);
    k_pool<<<NB, 256>>>();
    k_sim<<<NB, 256>>>();
    k_rank<<<NB, SS>>>(ids, phid);
    k_loss<<<1, 64>>>(out + (size_t)out_size - 1);
    k_text<<<NB * SS, DT / 4>>>(wte, ids, out);
}

// round 3
// speedup vs baseline: 1.4589x; 1.4589x over previous
#include <cuda_runtime.h>
#include <cuda_bf16.h>
#include <math.h>
#include <stdint.h>

#define NB   64
#define PP   256
#define DV   1024
#define DT   768
#define SS   512
#define NSEG 32
#define PPT  8
#define MTOT 2048          // NB*NSEG rows
#define KST  2048          // stored K per row: [hi(1024) | lo(1024)]
#define NSEGK 3            // hi*hi, hi*lo, lo*hi
#define NKIT  96           // 3*1024/32 K-iterations of BK=32

// ---------------- scratch --------------------------------------------------
static __device__ __nv_bfloat16 g_asplit[MTOT * KST];  // 8 MB
static __device__ __nv_bfloat16 g_bsplit[DT * KST];    // 3 MB
static __device__ float g_segmean[MTOT * DT];          // 6 MB
static __device__ float g_nrm[NB * DT];
static __device__ float g_sim[NB * NB];
static __device__ int   g_rank[NB * SS];

__device__ __forceinline__ unsigned pack_bf2(float x, float y) {
    __nv_bfloat162 p = __floats2bfloat162_rn(x, y);
    unsigned u; memcpy(&u, &p, 4);
    return u;
}
__device__ __forceinline__ uint32_t smem_u32(const void* p) {
    uint32_t a;
    asm("{ .reg .u64 t; cvta.to.shared.u64 t, %1; cvt.u32.u64 %0, t; }" : "=r"(a) : "l"(p));
    return a;
}
__device__ __forceinline__ void cp16(uint32_t d, const void* s) {
    asm volatile("cp.async.cg.shared.global [%0], [%1], 16;" :: "r"(d), "l"(s) : "memory");
}
#define CP_COMMIT() asm volatile("cp.async.commit_group;" ::: "memory")
#define CP_WAIT2()  asm volatile("cp.async.wait_group 2;" ::: "memory")
__device__ __forceinline__ void ldsm_x4(uint32_t* r, uint32_t a) {
    asm volatile("ldmatrix.sync.aligned.m8n8.x4.shared.b16 {%0,%1,%2,%3}, [%4];"
                 : "=r"(r[0]), "=r"(r[1]), "=r"(r[2]), "=r"(r[3]) : "r"(a));
}
__device__ __forceinline__ void mma16816(float* d, const uint32_t* a, const uint32_t* b) {
    asm volatile("mma.sync.aligned.m16n8k16.row.col.f32.bf16.bf16.f32 "
                 "{%0,%1,%2,%3}, {%4,%5,%6,%7}, {%8,%9}, {%0,%1,%2,%3};"
                 : "+f"(d[0]), "+f"(d[1]), "+f"(d[2]), "+f"(d[3])
                 : "r"(a[0]), "r"(a[1]), "r"(a[2]), "r"(a[3]), "r"(b[0]), "r"(b[1]));
}

// ---------------- 1) LayerNorm + segment sum -> bf16 hi/lo split ------------
__global__ void k_ln_segsum(const float* __restrict__ vis,
                            const float* __restrict__ gamma,
                            const float* __restrict__ beta) {
    int bs = blockIdx.x, tid = threadIdx.x;
    int lane = tid & 31, warp = tid >> 5;
    __shared__ float rs[8], rq[8], bc[2];
    const float* base = vis + (size_t)bs * PPT * DV;
    int d0 = tid * 4;
    float4 g  = *(const float4*)(gamma + d0);
    float4 be = *(const float4*)(beta  + d0);
    float a0 = 0.f, a1 = 0.f, a2 = 0.f, a3 = 0.f;
    for (int p = 0; p < PPT; ++p) {
        float4 x = *(const float4*)(base + p * DV + d0);
        float s = x.x + x.y + x.z + x.w;
        float q = x.x * x.x + x.y * x.y + x.z * x.z + x.w * x.w;
        #pragma unroll
        for (int o = 16; o > 0; o >>= 1) {
            s += __shfl_xor_sync(0xffffffffu, s, o);
            q += __shfl_xor_sync(0xffffffffu, q, o);
        }
        if (lane == 0) { rs[warp] = s; rq[warp] = q; }
        __syncthreads();
        if (warp == 0) {
            float s2 = lane < 8 ? rs[lane] : 0.f;
            float q2 = lane < 8 ? rq[lane] : 0.f;
            #pragma unroll
            for (int o = 4; o > 0; o >>= 1) {
                s2 += __shfl_xor_sync(0xffffffffu, s2, o);
                q2 += __shfl_xor_sync(0xffffffffu, q2, o);
            }
            if (lane == 0) {
                float mean = s2 * (1.f / DV);
                float var  = q2 * (1.f / DV) - mean * mean;
                bc[0] = mean; bc[1] = rsqrtf(var + 1e-5f);
            }
        }
        __syncthreads();
        float mean = bc[0], rstd = bc[1];
        a0 += (x.x - mean) * rstd * g.x + be.x;
        a1 += (x.y - mean) * rstd * g.y + be.y;
        a2 += (x.z - mean) * rstd * g.z + be.z;
        a3 += (x.w - mean) * rstd * g.w + be.w;
    }
    float v[4] = {a0, a1, a2, a3}, lo[4];
    #pragma unroll
    for (int c = 0; c < 4; ++c)
        lo[c] = v[c] - __bfloat162float(__float2bfloat16_rn(v[c]));
    size_t rowb = (size_t)bs * KST + d0;
    *(uint2*)(g_asplit + rowb)        = make_uint2(pack_bf2(v[0],  v[1]),  pack_bf2(v[2],  v[3]));
    *(uint2*)(g_asplit + rowb + 1024) = make_uint2(pack_bf2(lo[0], lo[1]), pack_bf2(lo[2], lo[3]));
}

// ---------------- 2a) W [1024,768] -> W^T hi/lo [768, 2048] bf16 ------------
__global__ void k_wsplit(const float* __restrict__ W) {
    __shared__ float t[32][33];
    int n0 = blockIdx.x * 32, k0 = blockIdx.y * 32;
    int tx = threadIdx.x, ty = threadIdx.y;  // 32 x 8
    #pragma unroll
    for (int i = 0; i < 4; ++i)
        t[ty + 8 * i][tx] = W[(size_t)(k0 + ty + 8 * i) * DT + n0 + tx];
    __syncthreads();
    #pragma unroll
    for (int i = 0; i < 4; ++i) {
        int n = n0 + ty + 8 * i;
        float v = t[tx][ty + 8 * i];                 // = W[k0+tx][n]
        float lo = v - __bfloat162float(__float2bfloat16_rn(v));
        size_t rowb = (size_t)n * KST + k0 + tx;
        g_bsplit[rowb]        = __float2bfloat16_rn(v);
        g_bsplit[rowb + 1024] = __float2bfloat16_rn(lo);
    }
}

// ---------------- 2b) mma.sync bf16 GEMM ------------------------------------
// D[2048,768] = sum over 3 segments of A' @ B'^T, * 0.125 + bproj
// BM=128 BN=96 BK=32, 8 warps (4 wm x 2 wn), 3-stage cp.async pipeline.
// smem row stride 80B: conflict-free ldmatrix without XOR swizzle.
#define ABYTES (128 * 80)
#define BBYTES (96 * 80)
#define STGB   (ABYTES + BBYTES)
__global__ __launch_bounds__(256, 1) void k_gemm_mma(const float* __restrict__ bproj) {
    extern __shared__ __align__(16) char sm[];
    uint32_t smb = smem_u32(sm);
    int tid = threadIdx.x, lane = tid & 31, wid = tid >> 5;
    int wm = wid & 3, wn = wid >> 2;
    int m0 = blockIdx.y * 128, n0 = blockIdx.x * 96;

    const __nv_bfloat16* gA = g_asplit + (size_t)m0 * KST;
    const __nv_bfloat16* gB = g_bsplit + (size_t)n0 * KST;

    auto prefetch = [&](int kb, int stg) {
        int seg = kb >> 5;
        int kin = (kb & 31) << 5;
        int ak = (seg == 2 ? 1024 : 0) + kin;
        int bk = (seg == 1 ? 1024 : 0) + kin;
        uint32_t stA = smb + stg * STGB;
        uint32_t stB = stA + ABYTES;
        // A: 128 rows x 64B = 512 x 16B chunks, 2 per thread
        #pragma unroll
        for (int i = 0; i < 2; ++i) {
            int ca = tid + i * 256;
            int r = ca >> 2, c = ca & 3;
            cp16(stA + r * 80 + c * 16, gA + (size_t)r * KST + ak + c * 8);
        }
        // B: 96 rows x 64B = 384 chunks
        {
            int r = tid >> 2, c = tid & 3;
            cp16(stB + r * 80 + c * 16, gB + (size_t)r * KST + bk + c * 8);
        }
        if (tid < 128) {
            int cb = tid + 256;
            int r = cb >> 2, c = cb & 3;
            cp16(stB + r * 80 + c * 16, gB + (size_t)r * KST + bk + c * 8);
        }
        CP_COMMIT();
    };

    float d[2][6][4];
    #pragma unroll
    for (int i = 0; i < 2; ++i)
        #pragma unroll
        for (int j = 0; j < 6; ++j)
            #pragma unroll
            for (int c = 0; c < 4; ++c) d[i][j][c] = 0.f;

    prefetch(0, 0);
    prefetch(1, 1);

    int aRow = (wm * 32 + (lane & 15)) * 80 + (lane >> 4) * 16;
    int bRow = (wn * 48 + (lane & 7) + ((lane >> 4) << 3)) * 80 + ((lane >> 3) & 1) * 16;

    for (int kb = 0; kb < NKIT; ++kb) {
        if (kb + 2 < NKIT) prefetch(kb + 2, (kb + 2) % 3);
        else CP_COMMIT();                        // keep group count invariant
        CP_WAIT2();
        __syncthreads();
        uint32_t stA = smb + (kb % 3) * STGB;
        uint32_t stB = stA + ABYTES;
        #pragma unroll
        for (int s = 0; s < 2; ++s) {            // two k16 steps in BK=32
            uint32_t a[2][4], b[3][4];
            #pragma unroll
            for (int mf = 0; mf < 2; ++mf)
                ldsm_x4(a[mf], stA + aRow + mf * 16 * 80 + s * 32);
            #pragma unroll
            for (int np = 0; np < 3; ++np)
                ldsm_x4(b[np], stB + bRow + np * 16 * 80 + s * 32);
            #pragma unroll
            for (int mf = 0; mf < 2; ++mf)
                #pragma unroll
                for (int nf = 0; nf < 6; ++nf)
                    mma16816(d[mf][nf], a[mf], &b[nf >> 1][(nf & 1) * 2]);
        }
        __syncthreads();
    }

    // epilogue: d * 0.125 + bias
    int grp = lane >> 2, tig = lane & 3;
    #pragma unroll
    for (int nf = 0; nf < 6; ++nf) {
        int n = n0 + wn * 48 + nf * 8 + tig * 2;
        float bp0 = __ldg(bproj + n), bp1 = __ldg(bproj + n + 1);
        #pragma unroll
        for (int mf = 0; mf < 2; ++mf) {
            int m = m0 + wm * 32 + mf * 16 + grp;
            float2 o0 = make_float2(d[mf][nf][0] * 0.125f + bp0,
                                    d[mf][nf][1] * 0.125f + bp1);
            float2 o1 = make_float2(d[mf][nf][2] * 0.125f + bp0,
                                    d[mf][nf][3] * 0.125f + bp1);
            *(float2*)(g_segmean + (size_t)m * DT + n)       = o0;
            *(float2*)(g_segmean + (size_t)(m + 8) * DT + n) = o1;
        }
    }
}

// ---------------- 3) pooled mean + L2 normalize -----------------------------
__global__ void k_pool() {
    int b = blockIdx.x, tid = threadIdx.x;
    int lane = tid & 31, warp = tid >> 5;
    __shared__ float red[8], bn;
    float p[3];
    #pragma unroll
    for (int c = 0; c < 3; ++c) {
        int d = tid + c * 256;
        float s = 0.f;
        for (int sg = 0; sg < NSEG; ++sg)
            s += g_segmean[((size_t)b * NSEG + sg) * DT + d];
        p[c] = s * (1.f / NSEG);
    }
    float q = p[0] * p[0] + p[1] * p[1] + p[2] * p[2];
    #pragma unroll
    for (int o = 16; o > 0; o >>= 1) q += __shfl_xor_sync(0xffffffffu, q, o);
    if (lane == 0) red[warp] = q;
    __syncthreads();
    if (warp == 0) {
        float q2 = lane < 8 ? red[lane] : 0.f;
        #pragma unroll
        for (int o = 4; o > 0; o >>= 1) q2 += __shfl_xor_sync(0xffffffffu, q2, o);
        if (lane == 0) bn = 1.f / sqrtf(q2);
    }
    __syncthreads();
    float inv = bn;
    #pragma unroll
    for (int c = 0; c < 3; ++c)
        g_nrm[(size_t)b * DT + tid + c * 256] = p[c] * inv;
}

// ---------------- 4) sim = (nrm @ nrm^T) / TEMP -----------------------------
__global__ void k_sim() {
    int i = blockIdx.y, jq = blockIdx.x;
    int tid = threadIdx.x, w = tid >> 5, lane = tid & 31;
    __shared__ float ni[DT];
    if (tid < 192)
        *(float4*)(ni + tid * 4) = *(const float4*)(g_nrm + (size_t)i * DT + tid * 4);
    __syncthreads();
    #pragma unroll
    for (int jj = 0; jj < 2; ++jj) {
        int j = jq * 16 + w * 2 + jj;
        const float4* nj = (const float4*)(g_nrm + (size_t)j * DT);
        float s = 0.f;
        #pragma unroll
        for (int it = 0; it < 6; ++it) {
            int d4 = lane + it * 32;
            float4 bb = nj[d4];
            float4 aa = *(const float4*)(ni + d4 * 4);
            s += aa.x * bb.x + aa.y * bb.y + aa.z * bb.z + aa.w * bb.w;
        }
        #pragma unroll
        for (int o = 16; o > 0; o >>= 1) s += __shfl_xor_sync(0xffffffffu, s, o);
        if (lane == 0) g_sim[i * NB + j] = s / 0.07f;
    }
}

// ---------------- 5) symmetric InfoNCE loss ---------------------------------
__global__ void k_loss(float* __restrict__ out) {
    int i = threadIdx.x;
    __shared__ float red[64];
    float diag = g_sim[i * NB + i];
    float m = -1e30f;
    for (int j = 0; j < NB; ++j) m = fmaxf(m, g_sim[i * NB + j]);
    float se = 0.f;
    for (int j = 0; j < NB; ++j) se += expf(g_sim[i * NB + j] - m);
    float rl = (m + logf(se)) - diag;
    float mc = -1e30f;
    for (int j = 0; j < NB; ++j) mc = fmaxf(mc, g_sim[j * NB + i]);
    float sc = 0.f;
    for (int j = 0; j < NB; ++j) sc += expf(g_sim[j * NB + i] - mc);
    float cl = (mc + logf(sc)) - diag;
    red[i] = rl + cl;
    __syncthreads();
    #pragma unroll
    for (int o = 32; o > 0; o >>= 1) {
        if (i < o) red[i] += red[i + o];
        __syncthreads();
    }
    if (i == 0) out[0] = red[0] * (0.5f / NB);
}

// ---------------- 6) per-row placeholder rank -------------------------------
__global__ void k_rank(const int* __restrict__ ids, const int* __restrict__ phid) {
    int b = blockIdx.x, s = threadIdx.x;
    __shared__ int sc[SS];
    int ph = phid[0];
    int m = (ids[b * SS + s] == ph) ? 1 : 0;
    sc[s] = m;
    __syncthreads();
    for (int o = 1; o < SS; o <<= 1) {
        int v = (s >= o) ? sc[s - o] : 0;
        __syncthreads();
        sc[s] += v;
        __syncthreads();
    }
    int rank = sc[s] - 1;
    g_rank[b * SS + s] = (m && rank < NSEG) ? rank : -1;
}

// ---------------- 7) text_emb assembly --------------------------------------
__global__ void k_text(const float* __restrict__ wte, const int* __restrict__ ids,
                       float* __restrict__ out) {
    int bs = blockIdx.x, tid = threadIdx.x;  // 192 threads * float4
    int r = g_rank[bs];
    const float4* src;
    if (r >= 0) {
        int b = bs / SS;
        src = (const float4*)(g_segmean + ((size_t)(b * NSEG + r)) * DT);
    } else {
        src = (const float4*)(wte + (size_t)ids[bs] * DT);
    }
    ((float4*)out)[(size_t)bs * (DT / 4) + tid] = src[tid];
}

// ---------------- launch ----------------------------------------------------
extern "C" void kernel_launch(void* const* d_in, const int* in_sizes, int n_in,
                              void* d_out, int out_size) {
    const float* vis   = (const float*)d_in[0];
    const float* gamma = (const float*)d_in[1];
    const float* beta  = (const float*)d_in[2];
    const float* W     = (const float*)d_in[3];
    const float* bproj = (const float*)d_in[4];
    const float* wte   = (const float*)d_in[5];
    const int*   ids   = (const int*)d_in[6];
    const int*   phid  = (const int*)d_in[7];
    float* out = (float*)d_out;

    static int smset = 0;
    if (!smset) {
        cudaFuncSetAttribute(k_gemm_mma, cudaFuncAttributeMaxDynamicSharedMemorySize,
                             3 * STGB);
        smset = 1;
    }

    k_ln_segsum<<<NB * NSEG, 256>>>(vis, gamma, beta);
    k_wsplit<<<dim3(DT / 32, DV / 32), dim3(32, 8)>>>(W);
    k_gemm_mma<<<dim3(DT / 96, MTOT / 128), 256, 3 * STGB>>>(bproj);
    k_pool<<<NB, 256>>>();
    k_sim<<<dim3(4, NB), 256>>>();
    k_rank<<<NB, SS>>>(ids, phid);
    k_loss<<<1, 64>>>(out + (size_t)out_size - 1);
    k_text<<<NB * SS, DT / 4>>>(wte, ids, out);
}

// round 4
// speedup vs baseline: 1.6860x; 1.1557x over previous
#include <cuda_runtime.h>
#include <cuda_bf16.h>
#include <math.h>
#include <stdint.h>

#define NB   64
#define PP   256
#define DV   1024
#define DT   768
#define SS   512
#define NSEG 32
#define PPT  8
#define MTOT 2048          // NB*NSEG rows
#define KST  2048          // stored K per row: [hi(1024) | lo(1024)]
#define NKIT 96            // 3*1024/32 K-iterations of BK=32
#define STAGES 8

// ---------------- scratch --------------------------------------------------
static __device__ __nv_bfloat16 g_asplit[MTOT * KST];  // 8 MB
static __device__ __nv_bfloat16 g_bsplit[DT * KST];    // 3 MB
static __device__ float g_segmean[MTOT * DT];          // 6 MB
static __device__ float g_nrm[NB * DT];
static __device__ float g_sim[NB * NB];
static __device__ int   g_rank[NB * SS];

__device__ __forceinline__ unsigned pack_bf2(float x, float y) {
    __nv_bfloat162 p = __floats2bfloat162_rn(x, y);
    unsigned u; memcpy(&u, &p, 4);
    return u;
}
__device__ __forceinline__ uint32_t smem_u32(const void* p) {
    uint32_t a;
    asm("{ .reg .u64 t; cvta.to.shared.u64 t, %1; cvt.u32.u64 %0, t; }" : "=r"(a) : "l"(p));
    return a;
}
__device__ __forceinline__ void cp16(uint32_t d, const void* s) {
    asm volatile("cp.async.cg.shared.global [%0], [%1], 16;" :: "r"(d), "l"(s) : "memory");
}
#define CP_COMMIT() asm volatile("cp.async.commit_group;" ::: "memory")
#define CP_WAIT6()  asm volatile("cp.async.wait_group 6;" ::: "memory")
__device__ __forceinline__ void ldsm_x4(uint32_t* r, uint32_t a) {
    asm volatile("ldmatrix.sync.aligned.m8n8.x4.shared.b16 {%0,%1,%2,%3}, [%4];"
                 : "=r"(r[0]), "=r"(r[1]), "=r"(r[2]), "=r"(r[3]) : "r"(a));
}
__device__ __forceinline__ void mma16816(float* d, const uint32_t* a, const uint32_t* b) {
    asm volatile("mma.sync.aligned.m16n8k16.row.col.f32.bf16.bf16.f32 "
                 "{%0,%1,%2,%3}, {%4,%5,%6,%7}, {%8,%9}, {%0,%1,%2,%3};"
                 : "+f"(d[0]), "+f"(d[1]), "+f"(d[2]), "+f"(d[3])
                 : "r"(a[0]), "r"(a[1]), "r"(a[2]), "r"(a[3]), "r"(b[0]), "r"(b[1]));
}

// ---------------- 1) LayerNorm + segment sum -> bf16 hi/lo split ------------
// Batched loads (MLP=8), one fused block reduce for all 8 patches.
__global__ __launch_bounds__(256) void k_ln_segsum(const float* __restrict__ vis,
                                                   const float* __restrict__ gamma,
                                                   const float* __restrict__ beta) {
    int bs = blockIdx.x, tid = threadIdx.x;
    int lane = tid & 31, warp = tid >> 5;
    __shared__ float rs[PPT][8], rq[PPT][8], bc2[PPT][2];
    const float* base = vis + (size_t)bs * PPT * DV;
    int d0 = tid * 4;

    float4 x[PPT];
    #pragma unroll
    for (int p = 0; p < PPT; ++p)
        x[p] = *(const float4*)(base + p * DV + d0);

    #pragma unroll
    for (int p = 0; p < PPT; ++p) {
        float s = x[p].x + x[p].y + x[p].z + x[p].w;
        float q = x[p].x * x[p].x + x[p].y * x[p].y + x[p].z * x[p].z + x[p].w * x[p].w;
        #pragma unroll
        for (int o = 16; o > 0; o >>= 1) {
            s += __shfl_xor_sync(0xffffffffu, s, o);
            q += __shfl_xor_sync(0xffffffffu, q, o);
        }
        if (lane == 0) { rs[p][warp] = s; rq[p][warp] = q; }
    }
    __syncthreads();
    if (warp == 0) {
        int p = lane & 7, h = lane >> 3;               // h in 0..3
        float s2 = rs[p][h] + rs[p][h + 4];
        float q2 = rq[p][h] + rq[p][h + 4];
        s2 += __shfl_xor_sync(0xffffffffu, s2, 8);
        q2 += __shfl_xor_sync(0xffffffffu, q2, 8);
        s2 += __shfl_xor_sync(0xffffffffu, s2, 16);
        q2 += __shfl_xor_sync(0xffffffffu, q2, 16);
        if (lane < 8) {
            float mean = s2 * (1.f / DV);
            float var  = q2 * (1.f / DV) - mean * mean;
            bc2[p][0] = mean;
            bc2[p][1] = rsqrtf(var + 1e-5f);
        }
    }
    __syncthreads();

    float4 g  = *(const float4*)(gamma + d0);
    float4 be = *(const float4*)(beta  + d0);
    float a0 = 0.f, a1 = 0.f, a2 = 0.f, a3 = 0.f;
    #pragma unroll
    for (int p = 0; p < PPT; ++p) {
        float mean = bc2[p][0], rstd = bc2[p][1];
        a0 += (x[p].x - mean) * rstd * g.x + be.x;
        a1 += (x[p].y - mean) * rstd * g.y + be.y;
        a2 += (x[p].z - mean) * rstd * g.z + be.z;
        a3 += (x[p].w - mean) * rstd * g.w + be.w;
    }
    float v[4] = {a0, a1, a2, a3}, lo[4];
    #pragma unroll
    for (int c = 0; c < 4; ++c)
        lo[c] = v[c] - __bfloat162float(__float2bfloat16_rn(v[c]));
    size_t rowb = (size_t)bs * KST + d0;
    *(uint2*)(g_asplit + rowb)        = make_uint2(pack_bf2(v[0],  v[1]),  pack_bf2(v[2],  v[3]));
    *(uint2*)(g_asplit + rowb + 1024) = make_uint2(pack_bf2(lo[0], lo[1]), pack_bf2(lo[2], lo[3]));
}

// ---------------- 2a) W [1024,768] -> W^T hi/lo [768, 2048] bf16 ------------
__global__ void k_wsplit(const float* __restrict__ W) {
    __shared__ float t[32][33];
    int n0 = blockIdx.x * 32, k0 = blockIdx.y * 32;
    int tx = threadIdx.x, ty = threadIdx.y;  // 32 x 8
    #pragma unroll
    for (int i = 0; i < 4; ++i)
        t[ty + 8 * i][tx] = W[(size_t)(k0 + ty + 8 * i) * DT + n0 + tx];
    __syncthreads();
    #pragma unroll
    for (int i = 0; i < 4; ++i) {
        int n = n0 + ty + 8 * i;
        float v = t[tx][ty + 8 * i];                 // = W[k0+tx][n]
        float lo = v - __bfloat162float(__float2bfloat16_rn(v));
        size_t rowb = (size_t)n * KST + k0 + tx;
        g_bsplit[rowb]        = __float2bfloat16_rn(v);
        g_bsplit[rowb + 1024] = __float2bfloat16_rn(lo);
    }
}

// ---------------- 2b) mma.sync bf16 GEMM, 8-stage pipeline ------------------
// D[2048,768] = sum over 3 segments of A' @ B'^T, * 0.125 + bproj
// BM=128 BN=96 BK=32, 8 warps (4 wm x 2 wn). smem row stride 80B.
#define ABYTES (128 * 80)
#define BBYTES (96 * 80)
#define STGB   (ABYTES + BBYTES)
__global__ __launch_bounds__(256, 1) void k_gemm_mma(const float* __restrict__ bproj) {
    extern __shared__ __align__(16) char sm[];
    uint32_t smb = smem_u32(sm);
    int tid = threadIdx.x, lane = tid & 31, wid = tid >> 5;
    int wm = wid & 3, wn = wid >> 2;
    int m0 = blockIdx.y * 128, n0 = blockIdx.x * 96;

    const __nv_bfloat16* gA = g_asplit + (size_t)m0 * KST;
    const __nv_bfloat16* gB = g_bsplit + (size_t)n0 * KST;

    auto prefetch = [&](int kb, int stg) {
        int seg = kb >> 5;
        int kin = (kb & 31) << 5;
        int ak = (seg == 2 ? 1024 : 0) + kin;
        int bk = (seg == 1 ? 1024 : 0) + kin;
        uint32_t stA = smb + stg * STGB;
        uint32_t stB = stA + ABYTES;
        #pragma unroll
        for (int i = 0; i < 2; ++i) {
            int ca = tid + i * 256;
            int r = ca >> 2, c = ca & 3;
            cp16(stA + r * 80 + c * 16, gA + (size_t)r * KST + ak + c * 8);
        }
        {
            int r = tid >> 2, c = tid & 3;
            cp16(stB + r * 80 + c * 16, gB + (size_t)r * KST + bk + c * 8);
        }
        if (tid < 128) {
            int cb = tid + 256;
            int r = cb >> 2, c = cb & 3;
            cp16(stB + r * 80 + c * 16, gB + (size_t)r * KST + bk + c * 8);
        }
        CP_COMMIT();
    };

    float d[2][6][4];
    #pragma unroll
    for (int i = 0; i < 2; ++i)
        #pragma unroll
        for (int j = 0; j < 6; ++j)
            #pragma unroll
            for (int c = 0; c < 4; ++c) d[i][j][c] = 0.f;

    #pragma unroll
    for (int s = 0; s < STAGES - 1; ++s) prefetch(s, s);   // 7 groups pending

    int aRow = (wm * 32 + (lane & 15)) * 80 + (lane >> 4) * 16;
    int bRow = (wn * 48 + (lane & 7) + ((lane >> 4) << 3)) * 80 + ((lane >> 3) & 1) * 16;

    for (int kb = 0; kb < NKIT; ++kb) {
        CP_WAIT6();                 // invariant: 7 pending -> oldest (stage kb) done
        __syncthreads();            // all warps done reading stage (kb-1)%8 too
        if (kb + STAGES - 1 < NKIT) prefetch(kb + STAGES - 1, (kb + STAGES - 1) & 7);
        else CP_COMMIT();           // keep pending-count invariant
        uint32_t stA = smb + (kb & 7) * STGB;
        uint32_t stB = stA + ABYTES;
        #pragma unroll
        for (int s = 0; s < 2; ++s) {
            uint32_t a[2][4], b[3][4];
            #pragma unroll
            for (int mf = 0; mf < 2; ++mf)
                ldsm_x4(a[mf], stA + aRow + mf * 16 * 80 + s * 32);
            #pragma unroll
            for (int np = 0; np < 3; ++np)
                ldsm_x4(b[np], stB + bRow + np * 16 * 80 + s * 32);
            #pragma unroll
            for (int mf = 0; mf < 2; ++mf)
                #pragma unroll
                for (int nf = 0; nf < 6; ++nf)
                    mma16816(d[mf][nf], a[mf], &b[nf >> 1][(nf & 1) * 2]);
        }
    }

    int grp = lane >> 2, tig = lane & 3;
    #pragma unroll
    for (int nf = 0; nf < 6; ++nf) {
        int n = n0 + wn * 48 + nf * 8 + tig * 2;
        float bp0 = __ldg(bproj + n), bp1 = __ldg(bproj + n + 1);
        #pragma unroll
        for (int mf = 0; mf < 2; ++mf) {
            int m = m0 + wm * 32 + mf * 16 + grp;
            float2 o0 = make_float2(d[mf][nf][0] * 0.125f + bp0,
                                    d[mf][nf][1] * 0.125f + bp1);
            float2 o1 = make_float2(d[mf][nf][2] * 0.125f + bp0,
                                    d[mf][nf][3] * 0.125f + bp1);
            *(float2*)(g_segmean + (size_t)m * DT + n)       = o0;
            *(float2*)(g_segmean + (size_t)(m + 8) * DT + n) = o1;
        }
    }
}

// ---------------- 3) pooled mean + L2 normalize (768 thr, thread-per-dim) ---
__global__ __launch_bounds__(768) void k_pool() {
    int b = blockIdx.x, tid = threadIdx.x;   // tid = dim
    int lane = tid & 31, warp = tid >> 5;    // 24 warps
    __shared__ float red[24];
    __shared__ float bn;
    const float* src = g_segmean + (size_t)b * NSEG * DT + tid;
    float s = 0.f;
    #pragma unroll
    for (int sg = 0; sg < NSEG; ++sg) s += src[sg * DT];
    float p = s * (1.f / NSEG);
    float q = p * p;
    #pragma unroll
    for (int o = 16; o > 0; o >>= 1) q += __shfl_xor_sync(0xffffffffu, q, o);
    if (lane == 0) red[warp] = q;
    __syncthreads();
    if (warp == 0) {
        float q2 = lane < 24 ? red[lane] : 0.f;
        #pragma unroll
        for (int o = 16; o > 0; o >>= 1) q2 += __shfl_xor_sync(0xffffffffu, q2, o);
        if (lane == 0) bn = 1.f / sqrtf(q2);
    }
    __syncthreads();
    g_nrm[(size_t)b * DT + tid] = p * bn;
}

// ---------------- 4) sim = (nrm @ nrm^T) / TEMP -----------------------------
__global__ void k_sim() {
    int i = blockIdx.y, jq = blockIdx.x;
    int tid = threadIdx.x, w = tid >> 5, lane = tid & 31;
    __shared__ float ni[DT];
    if (tid < 192)
        *(float4*)(ni + tid * 4) = *(const float4*)(g_nrm + (size_t)i * DT + tid * 4);
    __syncthreads();
    #pragma unroll
    for (int jj = 0; jj < 2; ++jj) {
        int j = jq * 16 + w * 2 + jj;
        const float4* nj = (const float4*)(g_nrm + (size_t)j * DT);
        float s = 0.f;
        #pragma unroll
        for (int it = 0; it < 6; ++it) {
            int d4 = lane + it * 32;
            float4 bb = nj[d4];
            float4 aa = *(const float4*)(ni + d4 * 4);
            s += aa.x * bb.x + aa.y * bb.y + aa.z * bb.z + aa.w * bb.w;
        }
        #pragma unroll
        for (int o = 16; o > 0; o >>= 1) s += __shfl_xor_sync(0xffffffffu, s, o);
        if (lane == 0) g_sim[i * NB + j] = s / 0.07f;
    }
}

// ---------------- 5) symmetric InfoNCE loss ---------------------------------
__global__ void k_loss(float* __restrict__ out) {
    int i = threadIdx.x;
    __shared__ float red[64];
    float diag = g_sim[i * NB + i];
    float m = -1e30f;
    for (int j = 0; j < NB; ++j) m = fmaxf(m, g_sim[i * NB + j]);
    float se = 0.f;
    for (int j = 0; j < NB; ++j) se += expf(g_sim[i * NB + j] - m);
    float rl = (m + logf(se)) - diag;
    float mc = -1e30f;
    for (int j = 0; j < NB; ++j) mc = fmaxf(mc, g_sim[j * NB + i]);
    float sc = 0.f;
    for (int j = 0; j < NB; ++j) sc += expf(g_sim[j * NB + i] - mc);
    float cl = (mc + logf(sc)) - diag;
    red[i] = rl + cl;
    __syncthreads();
    #pragma unroll
    for (int o = 32; o > 0; o >>= 1) {
        if (i < o) red[i] += red[i + o];
        __syncthreads();
    }
    if (i == 0) out[0] = red[0] * (0.5f / NB);
}

// ---------------- 6) per-row placeholder rank -------------------------------
__global__ void k_rank(const int* __restrict__ ids, const int* __restrict__ phid) {
    int b = blockIdx.x, s = threadIdx.x;
    __shared__ int sc[SS];
    int ph = phid[0];
    int m = (ids[b * SS + s] == ph) ? 1 : 0;
    sc[s] = m;
    __syncthreads();
    for (int o = 1; o < SS; o <<= 1) {
        int v = (s >= o) ? sc[s - o] : 0;
        __syncthreads();
        sc[s] += v;
        __syncthreads();
    }
    int rank = sc[s] - 1;
    g_rank[b * SS + s] = (m && rank < NSEG) ? rank : -1;
}

// ---------------- 7) text_emb assembly --------------------------------------
__global__ void k_text(const float* __restrict__ wte, const int* __restrict__ ids,
                       float* __restrict__ out) {
    int bs = blockIdx.x, tid = threadIdx.x;  // 192 threads * float4
    int r = g_rank[bs];
    const float4* src;
    if (r >= 0) {
        int b = bs / SS;
        src = (const float4*)(g_segmean + ((size_t)(b * NSEG + r)) * DT);
    } else {
        src = (const float4*)(wte + (size_t)ids[bs] * DT);
    }
    ((float4*)out)[(size_t)bs * (DT / 4) + tid] = src[tid];
}

// ---------------- launch ----------------------------------------------------
extern "C" void kernel_launch(void* const* d_in, const int* in_sizes, int n_in,
                              void* d_out, int out_size) {
    const float* vis   = (const float*)d_in[0];
    const float* gamma = (const float*)d_in[1];
    const float* beta  = (const float*)d_in[2];
    const float* W     = (const float*)d_in[3];
    const float* bproj = (const float*)d_in[4];
    const float* wte   = (const float*)d_in[5];
    const int*   ids   = (const int*)d_in[6];
    const int*   phid  = (const int*)d_in[7];
    float* out = (float*)d_out;

    cudaFuncSetAttribute(k_gemm_mma, cudaFuncAttributeMaxDynamicSharedMemorySize,
                         STAGES * STGB);

    k_ln_segsum<<<NB * NSEG, 256>>>(vis, gamma, beta);
    k_wsplit<<<dim3(DT / 32, DV / 32), dim3(32, 8)>>>(W);
    k_gemm_mma<<<dim3(DT / 96, MTOT / 128), 256, STAGES * STGB>>>(bproj);
    k_pool<<<NB, 768>>>();
    k_sim<<<dim3(4, NB), 256>>>();
    k_rank<<<NB, SS>>>(ids, phid);
    k_loss<<<1, 64>>>(out + (size_t)out_size - 1);
    k_text<<<NB * SS, DT / 4>>>(wte, ids, out);
}